// round 6
// baseline (speedup 1.0000x reference)
#include <cuda_runtime.h>
#include <cstdint>

#define BB 64
#define TT 4000
#define FF 128
#define ROWS_PER_BLOCK 32   // 8 warps * 4 rows each

struct SampleParams {
    int valid_t;
    int ts0, te0, ts1, te1;
    unsigned fm[4];   // 128-bit freq mask
    int pad[3];       // 48B
};

__device__ SampleParams g_params[BB];

// ================= compile-time Threefry-2x32 (20 rounds) =================
struct TF2 { unsigned a, b; };

__host__ __device__ constexpr unsigned rotl_c(unsigned x, int r) {
    return (x << r) | (x >> (32 - r));
}

__host__ __device__ constexpr TF2 tf2_c(unsigned k0, unsigned k1,
                                        unsigned x0, unsigned x1) {
    unsigned ks2 = k0 ^ k1 ^ 0x1BD11BDAu;
    x0 += k0; x1 += k1;
    x0 += x1; x1 = rotl_c(x1, 13) ^ x0;
    x0 += x1; x1 = rotl_c(x1, 15) ^ x0;
    x0 += x1; x1 = rotl_c(x1, 26) ^ x0;
    x0 += x1; x1 = rotl_c(x1,  6) ^ x0;
    x0 += k1;  x1 += ks2 + 1u;
    x0 += x1; x1 = rotl_c(x1, 17) ^ x0;
    x0 += x1; x1 = rotl_c(x1, 29) ^ x0;
    x0 += x1; x1 = rotl_c(x1, 16) ^ x0;
    x0 += x1; x1 = rotl_c(x1, 24) ^ x0;
    x0 += ks2; x1 += k0 + 2u;
    x0 += x1; x1 = rotl_c(x1, 13) ^ x0;
    x0 += x1; x1 = rotl_c(x1, 15) ^ x0;
    x0 += x1; x1 = rotl_c(x1, 26) ^ x0;
    x0 += x1; x1 = rotl_c(x1,  6) ^ x0;
    x0 += k0;  x1 += k1 + 3u;
    x0 += x1; x1 = rotl_c(x1, 17) ^ x0;
    x0 += x1; x1 = rotl_c(x1, 29) ^ x0;
    x0 += x1; x1 = rotl_c(x1, 16) ^ x0;
    x0 += x1; x1 = rotl_c(x1, 24) ^ x0;
    x0 += k1;  x1 += ks2 + 4u;
    x0 += x1; x1 = rotl_c(x1, 13) ^ x0;
    x0 += x1; x1 = rotl_c(x1, 15) ^ x0;
    x0 += x1; x1 = rotl_c(x1, 26) ^ x0;
    x0 += x1; x1 = rotl_c(x1,  6) ^ x0;
    x0 += ks2; x1 += k0 + 5u;
    return TF2{x0, x1};
}

// key(42) -> split 4 derived keys (counter-mode counts (0, i))
constexpr TF2 KFW = tf2_c(0u, 42u, 0u, 0u);
constexpr TF2 KFS = tf2_c(0u, 42u, 0u, 1u);
constexpr TF2 KTW = tf2_c(0u, 42u, 0u, 2u);
constexpr TF2 KTS = tf2_c(0u, 42u, 0u, 3u);
// randint internally splits kf_w into two streams
constexpr TF2 KA  = tf2_c(KFW.a, KFW.b, 0u, 0u);
constexpr TF2 KB  = tf2_c(KFW.a, KFW.b, 0u, 1u);

// ====================== runtime Threefry (leaf draws) ======================
__device__ __forceinline__ void tf2x32(unsigned k0, unsigned k1,
                                       unsigned x0, unsigned x1,
                                       unsigned &o0, unsigned &o1) {
    unsigned ks2 = k0 ^ k1 ^ 0x1BD11BDAu;
    x0 += k0; x1 += k1;
#define TF_R(r) { x0 += x1; x1 = (x1 << (r)) | (x1 >> (32 - (r))); x1 ^= x0; }
    TF_R(13) TF_R(15) TF_R(26) TF_R(6)
    x0 += k1;  x1 += ks2 + 1u;
    TF_R(17) TF_R(29) TF_R(16) TF_R(24)
    x0 += ks2; x1 += k0 + 2u;
    TF_R(13) TF_R(15) TF_R(26) TF_R(6)
    x0 += k0;  x1 += k1 + 3u;
    TF_R(17) TF_R(29) TF_R(16) TF_R(24)
    x0 += k1;  x1 += ks2 + 4u;
    TF_R(13) TF_R(15) TF_R(26) TF_R(6)
    x0 += ks2; x1 += k0 + 5u;
#undef TF_R
    o0 = x0; o1 = x1;
}

__device__ __forceinline__ unsigned rb32(unsigned k0, unsigned k1, unsigned i) {
    unsigned a, b; tf2x32(k0, k1, 0u, i, a, b);
    return a ^ b;
}
__device__ __forceinline__ unsigned long long rb64(unsigned k0, unsigned k1, unsigned i) {
    unsigned a, b; tf2x32(k0, k1, 0u, i, a, b);
    return ((unsigned long long)a << 32) | (unsigned long long)b;
}
__device__ __forceinline__ float u32_to_f(unsigned bits) {
    return __uint_as_float((bits >> 9) | 0x3F800000u) - 1.0f;
}
__device__ __forceinline__ double u64_to_d(unsigned long long bits) {
    return __longlong_as_double((long long)((bits >> 12) | 0x3FF0000000000000ULL)) - 1.0;
}

// ---------------- Setup: compute per-sample mask params (bit-exact R1) ----
__global__ void setup_kernel(const void* __restrict__ lengths_raw) {
    __shared__ int s_is64;
    int b = threadIdx.x;
    if (b == 0) {
        const unsigned long long* p = (const unsigned long long*)lengths_raw;
        unsigned long long m = 0;
        #pragma unroll
        for (int i = 0; i < 32; i++) m |= p[i];
        s_is64 = (m < 4096ULL);
    }
    __syncthreads();
    if (b >= BB) return;
    const int is64 = s_is64;

    int valid_t = is64 ? (int)((const long long*)lengths_raw)[b]
                       : ((const int*)lengths_raw)[b];

    unsigned fm[4] = {0u,0u,0u,0u};
    const int twmax = valid_t < 40 ? valid_t : 40;
    int ts[2], te[2];

    #pragma unroll
    for (int j = 0; j < 2; j++) {
        unsigned i = (unsigned)(b * 2 + j);
        int w, fs, tw, tstart;
        if (!is64) {
            unsigned hb = rb32(KA.a, KA.b, i);
            unsigned lb = rb32(KB.a, KB.b, i);
            w  = (int)(((hb % 31u) * 4u + (lb % 31u)) % 31u);
            float fu = u32_to_f(rb32(KFS.a, KFS.b, i));
            fs = (int)floorf(fu * (float)(FF - w + 1));
            float tu = u32_to_f(rb32(KTW.a, KTW.b, i));
            tw = (int)floorf(tu * (float)(twmax + 1));
            if (tw > twmax) tw = twmax;
            int sr = valid_t - tw + 1; if (sr < 1) sr = 1;
            float su = u32_to_f(rb32(KTS.a, KTS.b, i));
            tstart = (int)floorf(su * (float)sr);
        } else {
            unsigned long long hb = rb64(KA.a, KA.b, i);
            unsigned long long lb = rb64(KB.a, KB.b, i);
            w  = (int)(((hb % 31ULL) * 16ULL + (lb % 31ULL)) % 31ULL);
            double fu = u64_to_d(rb64(KFS.a, KFS.b, i));
            fs = (int)floor(fu * (double)(float)(FF - w + 1));
            double tu = u64_to_d(rb64(KTW.a, KTW.b, i));
            tw = (int)floor(tu * (double)(float)(twmax + 1));
            if (tw > twmax) tw = twmax;
            int sr = valid_t - tw + 1; if (sr < 1) sr = 1;
            double su = u64_to_d(rb64(KTS.a, KTS.b, i));
            tstart = (int)floor(su * (double)(float)sr);
        }

        if (w > 0 && w < FF) {
            const int lo = fs, hi = fs + w;
            #pragma unroll
            for (int k = 0; k < 4; k++) {
                int a = lo - 32 * k; if (a < 0) a = 0;
                int e = hi - 32 * k; if (e > 32) e = 32;
                if (a < e) {
                    unsigned mm = (e == 32) ? 0xFFFFFFFFu : ((1u << e) - 1u);
                    if (a > 0) mm &= ~((1u << a) - 1u);
                    fm[k] |= mm;
                }
            }
        }

        const bool tvalid = (tw > 0) && (tw < valid_t) && (valid_t > 0);
        ts[j] = tvalid ? tstart : 0;
        te[j] = tvalid ? tstart + tw : 0;
    }

    SampleParams sp;
    sp.valid_t = valid_t;
    sp.ts0 = ts[0]; sp.te0 = te[0];
    sp.ts1 = ts[1]; sp.te1 = te[1];
    sp.fm[0] = fm[0]; sp.fm[1] = fm[1]; sp.fm[2] = fm[2]; sp.fm[3] = fm[3];
    sp.pad[0] = sp.pad[1] = sp.pad[2] = 0;
    g_params[b] = sp;
}

// ---------------- Main: pure streaming masked copy -------------------------
__global__ void __launch_bounds__(256)
mask_kernel(const float4* __restrict__ src, float4* __restrict__ dst) {
    const int b    = blockIdx.y;
    const int tid  = threadIdx.x;
    const int warp = tid >> 5;
    const int lane = tid & 31;
    const int t0   = blockIdx.x * ROWS_PER_BLOCK + warp * 4;

    // issue the 4 data loads first (independent LDG.128, MLP=4)
    const size_t base = ((size_t)b * TT + t0) * (FF / 4) + lane;
    float4 v0 = src[base];
    float4 v1 = src[base + 32];
    float4 v2 = src[base + 64];
    float4 v3 = src[base + 96];

    // param loads: tiny, L1/L2-cached broadcasts
    const SampleParams* p = &g_params[b];
    const int vt  = __ldg(&p->valid_t);
    const int ts0 = __ldg(&p->ts0), te0 = __ldg(&p->te0);
    const int ts1 = __ldg(&p->ts1), te1 = __ldg(&p->te1);
    const unsigned word = __ldg(&p->fm[lane >> 3]);
    const unsigned nib  = (word >> ((lane & 7) << 2)) & 0xFu;

    #pragma unroll
    for (int k = 0; k < 4; k++) {
        float4 v = (k == 0) ? v0 : (k == 1) ? v1 : (k == 2) ? v2 : v3;
        const int t = t0 + k;
        const bool tm = (t >= ts0 && t < te0) || (t >= ts1 && t < te1);
        if (tm) {
            v.x = 0.0f; v.y = 0.0f; v.z = 0.0f; v.w = 0.0f;
        } else if (t < vt) {
            if (nib & 1u) v.x = 0.0f;
            if (nib & 2u) v.y = 0.0f;
            if (nib & 4u) v.z = 0.0f;
            if (nib & 8u) v.w = 0.0f;
        }
        dst[base + 32 * k] = v;
    }
}

extern "C" void kernel_launch(void* const* d_in, const int* in_sizes, int n_in,
                              void* d_out, int out_size) {
    const void* mel = d_in[0];
    const void* len = d_in[1];
    if (n_in >= 2 && in_sizes[0] == BB && in_sizes[1] != BB) {
        mel = d_in[1]; len = d_in[0];
    }

    setup_kernel<<<1, 64>>>(len);

    dim3 grid(TT / ROWS_PER_BLOCK, BB);   // (125, 64)
    mask_kernel<<<grid, 256>>>((const float4*)mel, (float4*)d_out);
}

// round 7
// speedup vs baseline: 1.0817x; 1.0817x over previous
#include <cuda_runtime.h>
#include <cstdint>

#define BB 64
#define TT 4000
#define FF 128
#define ROWS_PER_BLOCK 32   // 8 warps * 4 rows each

// ================= compile-time Threefry-2x32 (20 rounds) =================
struct TF2 { unsigned a, b; };

__host__ __device__ constexpr unsigned rotl_c(unsigned x, int r) {
    return (x << r) | (x >> (32 - r));
}

__host__ __device__ constexpr TF2 tf2_c(unsigned k0, unsigned k1,
                                        unsigned x0, unsigned x1) {
    unsigned ks2 = k0 ^ k1 ^ 0x1BD11BDAu;
    x0 += k0; x1 += k1;
    x0 += x1; x1 = rotl_c(x1, 13) ^ x0;
    x0 += x1; x1 = rotl_c(x1, 15) ^ x0;
    x0 += x1; x1 = rotl_c(x1, 26) ^ x0;
    x0 += x1; x1 = rotl_c(x1,  6) ^ x0;
    x0 += k1;  x1 += ks2 + 1u;
    x0 += x1; x1 = rotl_c(x1, 17) ^ x0;
    x0 += x1; x1 = rotl_c(x1, 29) ^ x0;
    x0 += x1; x1 = rotl_c(x1, 16) ^ x0;
    x0 += x1; x1 = rotl_c(x1, 24) ^ x0;
    x0 += ks2; x1 += k0 + 2u;
    x0 += x1; x1 = rotl_c(x1, 13) ^ x0;
    x0 += x1; x1 = rotl_c(x1, 15) ^ x0;
    x0 += x1; x1 = rotl_c(x1, 26) ^ x0;
    x0 += x1; x1 = rotl_c(x1,  6) ^ x0;
    x0 += k0;  x1 += k1 + 3u;
    x0 += x1; x1 = rotl_c(x1, 17) ^ x0;
    x0 += x1; x1 = rotl_c(x1, 29) ^ x0;
    x0 += x1; x1 = rotl_c(x1, 16) ^ x0;
    x0 += x1; x1 = rotl_c(x1, 24) ^ x0;
    x0 += k1;  x1 += ks2 + 4u;
    x0 += x1; x1 = rotl_c(x1, 13) ^ x0;
    x0 += x1; x1 = rotl_c(x1, 15) ^ x0;
    x0 += x1; x1 = rotl_c(x1, 26) ^ x0;
    x0 += x1; x1 = rotl_c(x1,  6) ^ x0;
    x0 += ks2; x1 += k0 + 5u;
    return TF2{x0, x1};
}

// key(42) -> split 4 derived keys (counter-mode counts (0, i))
constexpr TF2 KFW = tf2_c(0u, 42u, 0u, 0u);
constexpr TF2 KFS = tf2_c(0u, 42u, 0u, 1u);
constexpr TF2 KTW = tf2_c(0u, 42u, 0u, 2u);
constexpr TF2 KTS = tf2_c(0u, 42u, 0u, 3u);
// randint internally splits kf_w into two streams
constexpr TF2 KA  = tf2_c(KFW.a, KFW.b, 0u, 0u);
constexpr TF2 KB  = tf2_c(KFW.a, KFW.b, 0u, 1u);

// ====================== runtime Threefry (leaf draw) =======================
__device__ __forceinline__ void tf2x32(unsigned k0, unsigned k1,
                                       unsigned x0, unsigned x1,
                                       unsigned &o0, unsigned &o1) {
    unsigned ks2 = k0 ^ k1 ^ 0x1BD11BDAu;
    x0 += k0; x1 += k1;
#define TF_R(r) { x0 += x1; x1 = (x1 << (r)) | (x1 >> (32 - (r))); x1 ^= x0; }
    TF_R(13) TF_R(15) TF_R(26) TF_R(6)
    x0 += k1;  x1 += ks2 + 1u;
    TF_R(17) TF_R(29) TF_R(16) TF_R(24)
    x0 += ks2; x1 += k0 + 2u;
    TF_R(13) TF_R(15) TF_R(26) TF_R(6)
    x0 += k0;  x1 += k1 + 3u;
    TF_R(17) TF_R(29) TF_R(16) TF_R(24)
    x0 += k1;  x1 += ks2 + 4u;
    TF_R(13) TF_R(15) TF_R(26) TF_R(6)
    x0 += ks2; x1 += k0 + 5u;
#undef TF_R
    o0 = x0; o1 = x1;
}

__device__ __forceinline__ float u32_to_f(unsigned bits) {
    return __uint_as_float((bits >> 9) | 0x3F800000u) - 1.0f;
}
__device__ __forceinline__ double u64_to_d(unsigned long long bits) {
    return __longlong_as_double((long long)((bits >> 12) | 0x3FF0000000000000ULL)) - 1.0;
}

// ============================ fused kernel =================================
// Per-warp, barrier-free param compute (bit-exact, proven R5). Forced to
// 8 CTAs/SM via launch_bounds to deepen the per-SM LDG queue.
__global__ void __launch_bounds__(256, 8)
fused_kernel(const float4* __restrict__ src, float4* __restrict__ dst,
             const void* __restrict__ len_raw) {
    const int b    = blockIdx.y;
    const int tid  = threadIdx.x;
    const int warp = tid >> 5;
    const int lane = tid & 31;
    const int t0   = blockIdx.x * ROWS_PER_BLOCK + warp * 4;

    // ---- issue the block's data loads first (4 independent LDG.128) ----
    const size_t base = ((size_t)b * TT + t0) * (FF / 4) + lane;
    float4 v0 = src[base];
    float4 v1 = src[base + 32];
    float4 v2 = src[base + 64];
    float4 v3 = src[base + 96];

    // ---- dtype auto-detect (warp-parallel) ----
    const unsigned long long* lp = (const unsigned long long*)len_raw;
    unsigned long long q = 0;
    if (lane < 16) q = lp[lane];
    const unsigned small = __ballot_sync(0xFFFFFFFFu, q < 4096ULL);
    const bool is64 = ((small & 0xFFFFu) == 0xFFFFu);

    const long long v64 = ((const long long*)len_raw)[b];
    const int       v32 = ((const int*)len_raw)[b];
    const int vt = is64 ? (int)v64 : v32;

    // ---- 10 Threefry draws, one per lane (lanes 0..9) ----
    const int d = lane % 5;
    unsigned k0 = (d == 0) ? KA.a  : (d == 1) ? KB.a  : (d == 2) ? KFS.a
                 : (d == 3) ? KTW.a : KTS.a;
    unsigned k1 = (d == 0) ? KA.b  : (d == 1) ? KB.b  : (d == 2) ? KFS.b
                 : (d == 3) ? KTW.b : KTS.b;
    const unsigned ctr = (unsigned)(b * 2 + (lane >= 5 ? 1 : 0));
    unsigned oa, ob;
    tf2x32(k0, k1, 0u, ctr, oa, ob);
    const unsigned r32 = oa ^ ob;

    int ts[2], te[2];
    int fs[2], fe[2];
    const int twmax = vt < 40 ? vt : 40;

    #pragma unroll
    for (int j = 0; j < 2; j++) {
        const int L = j * 5;
        int w, fstart, tw, tstart;
        if (!is64) {
            unsigned ha = __shfl_sync(0xFFFFFFFFu, r32, L + 0);
            unsigned lb = __shfl_sync(0xFFFFFFFFu, r32, L + 1);
            unsigned uf = __shfl_sync(0xFFFFFFFFu, r32, L + 2);
            unsigned ut = __shfl_sync(0xFFFFFFFFu, r32, L + 3);
            unsigned us = __shfl_sync(0xFFFFFFFFu, r32, L + 4);
            w  = (int)(((ha % 31u) * 4u + (lb % 31u)) % 31u);
            fstart = (int)floorf(u32_to_f(uf) * (float)(FF - w + 1));
            tw = (int)floorf(u32_to_f(ut) * (float)(twmax + 1));
            if (tw > twmax) tw = twmax;
            int sr = vt - tw + 1; if (sr < 1) sr = 1;
            tstart = (int)floorf(u32_to_f(us) * (float)sr);
        } else {
            unsigned a0 = __shfl_sync(0xFFFFFFFFu, oa, L + 0);
            unsigned b0 = __shfl_sync(0xFFFFFFFFu, ob, L + 0);
            unsigned a1 = __shfl_sync(0xFFFFFFFFu, oa, L + 1);
            unsigned b1 = __shfl_sync(0xFFFFFFFFu, ob, L + 1);
            unsigned a2 = __shfl_sync(0xFFFFFFFFu, oa, L + 2);
            unsigned b2 = __shfl_sync(0xFFFFFFFFu, ob, L + 2);
            unsigned a3 = __shfl_sync(0xFFFFFFFFu, oa, L + 3);
            unsigned b3 = __shfl_sync(0xFFFFFFFFu, ob, L + 3);
            unsigned a4 = __shfl_sync(0xFFFFFFFFu, oa, L + 4);
            unsigned b4 = __shfl_sync(0xFFFFFFFFu, ob, L + 4);
            unsigned long long ha = ((unsigned long long)a0 << 32) | b0;
            unsigned long long lb = ((unsigned long long)a1 << 32) | b1;
            unsigned long long uf = ((unsigned long long)a2 << 32) | b2;
            unsigned long long ut = ((unsigned long long)a3 << 32) | b3;
            unsigned long long us = ((unsigned long long)a4 << 32) | b4;
            w  = (int)(((ha % 31ULL) * 16ULL + (lb % 31ULL)) % 31ULL);
            fstart = (int)floor(u64_to_d(uf) * (double)(float)(FF - w + 1));
            tw = (int)floor(u64_to_d(ut) * (double)(float)(twmax + 1));
            if (tw > twmax) tw = twmax;
            int sr = vt - tw + 1; if (sr < 1) sr = 1;
            tstart = (int)floor(u64_to_d(us) * (double)(float)sr);
        }

        const bool fvalid = (w > 0) && (w < FF);
        fs[j] = fvalid ? fstart : 0;
        fe[j] = fvalid ? fstart + w : 0;

        const bool tvalid = (tw > 0) && (tw < vt) && (vt > 0);
        ts[j] = tvalid ? tstart : 0;
        te[j] = tvalid ? tstart + tw : 0;
    }

    // per-lane freq mask for its 4 bins (same for all 4 rows)
    const int f = lane * 4;
    const bool fm0 = (f+0 >= fs[0] && f+0 < fe[0]) || (f+0 >= fs[1] && f+0 < fe[1]);
    const bool fm1 = (f+1 >= fs[0] && f+1 < fe[0]) || (f+1 >= fs[1] && f+1 < fe[1]);
    const bool fm2 = (f+2 >= fs[0] && f+2 < fe[0]) || (f+2 >= fs[1] && f+2 < fe[1]);
    const bool fm3 = (f+3 >= fs[0] && f+3 < fe[0]) || (f+3 >= fs[1] && f+3 < fe[1]);

    #pragma unroll
    for (int k = 0; k < 4; k++) {
        float4 v = (k == 0) ? v0 : (k == 1) ? v1 : (k == 2) ? v2 : v3;
        const int t = t0 + k;
        const bool tm = (t >= ts[0] && t < te[0]) || (t >= ts[1] && t < te[1]);
        if (tm) {
            v.x = 0.0f; v.y = 0.0f; v.z = 0.0f; v.w = 0.0f;
        } else if (t < vt) {
            if (fm0) v.x = 0.0f;
            if (fm1) v.y = 0.0f;
            if (fm2) v.z = 0.0f;
            if (fm3) v.w = 0.0f;
        }
        dst[base + 32 * k] = v;
    }
}

extern "C" void kernel_launch(void* const* d_in, const int* in_sizes, int n_in,
                              void* d_out, int out_size) {
    const void* mel = d_in[0];
    const void* len = d_in[1];
    if (n_in >= 2 && in_sizes[0] == BB && in_sizes[1] != BB) {
        mel = d_in[1]; len = d_in[0];
    }

    dim3 grid(TT / ROWS_PER_BLOCK, BB);   // (125, 64)
    fused_kernel<<<grid, 256>>>((const float4*)mel, (float4*)d_out, len);
}